// round 11
// baseline (speedup 1.0000x reference)
#include <cuda_runtime.h>
#include <cuda_bf16.h>
#include <math.h>

#define N_QUERIES 8192
#define N_WAY 5
#define DIM 256
#define WARPS_PER_BLOCK 8
#define GRID_BLOCKS (N_QUERIES / WARPS_PER_BLOCK)   // 1024

// Accumulators. Zero at module load; the last finishing block resets them
// after producing the output, so every graph replay starts from zero.
__device__ double       g_loss_sum = 0.0;
__device__ int          g_correct  = 0;
__device__ unsigned int g_ticket   = 0;

// Best-measured configuration (R3): plain float4 loads, default caching,
// compiler-chosen schedule at 32 regs / ~70% occupancy. Measured at the
// streaming floor: ~48.3MB / ~6.3TB/s + ~3.6us launch overhead.
__global__ __launch_bounds__(256) void proto_fused_kernel(
    const float* __restrict__ qry,      // [N, DIM]
    const float* __restrict__ prompt,   // [N*N_WAY, DIM]
    const float* __restrict__ labels,   // [N, N_WAY] one-hot
    float* __restrict__ out)            // [2]: loss, acc
{
    __shared__ float s_loss[WARPS_PER_BLOCK];
    __shared__ int   s_corr[WARPS_PER_BLOCK];

    const int warp_in_blk = threadIdx.x >> 5;
    const int lane        = threadIdx.x & 31;
    const int query       = blockIdx.x * WARPS_PER_BLOCK + warp_in_blk;

    const float4* q4 = reinterpret_cast<const float4*>(qry + (size_t)query * DIM);
    float4 qa = q4[lane];
    float4 qb = q4[lane + 32];

    float dist[N_WAY];
#pragma unroll
    for (int w = 0; w < N_WAY; ++w) {
        const float4* p4 = reinterpret_cast<const float4*>(
            prompt + ((size_t)query * N_WAY + w) * DIM);
        float4 pa = p4[lane];
        float4 pb = p4[lane + 32];
        float dx, s;
        dx = qa.x - pa.x; s  = dx * dx;
        dx = qa.y - pa.y; s = fmaf(dx, dx, s);
        dx = qa.z - pa.z; s = fmaf(dx, dx, s);
        dx = qa.w - pa.w; s = fmaf(dx, dx, s);
        dx = qb.x - pb.x; s = fmaf(dx, dx, s);
        dx = qb.y - pb.y; s = fmaf(dx, dx, s);
        dx = qb.z - pb.z; s = fmaf(dx, dx, s);
        dx = qb.w - pb.w; s = fmaf(dx, dx, s);
        dist[w] = s;
    }

    // Label fetch spread over 5 lanes; latency hides under the reduction.
    float lbl_v = (lane < N_WAY) ? labels[(size_t)query * N_WAY + lane] : 0.0f;
    unsigned int lbl_mask = __ballot_sync(0xFFFFFFFFu, lbl_v > 0.5f);

#pragma unroll
    for (int off = 16; off > 0; off >>= 1) {
#pragma unroll
        for (int w = 0; w < N_WAY; ++w)
            dist[w] += __shfl_xor_sync(0xFFFFFFFFu, dist[w], off);
    }

    if (lane == 0) {
        float mind = dist[0];
        int   amin = 0;
#pragma unroll
        for (int w = 1; w < N_WAY; ++w)
            if (dist[w] < mind) { mind = dist[w]; amin = w; }

        float sumexp = 0.0f;
#pragma unroll
        for (int w = 0; w < N_WAY; ++w)
            sumexp += __expf(mind - dist[w]);
        float lse = logf(sumexp);

        int label = __ffs(lbl_mask) - 1;           // the single set bit

        float logp = (mind - dist[label]) - lse;   // log_softmax at label
        s_loss[warp_in_blk] = -logp;
        s_corr[warp_in_blk] = (amin == label) ? 1 : 0;
    }
    __syncthreads();

    if (threadIdx.x == 0) {
        float bl = 0.0f;
        int   bc = 0;
#pragma unroll
        for (int i = 0; i < WARPS_PER_BLOCK; ++i) { bl += s_loss[i]; bc += s_corr[i]; }
        atomicAdd(&g_loss_sum, (double)bl);
        atomicAdd(&g_correct, bc);

        __threadfence();
        unsigned int t = atomicAdd(&g_ticket, 1u);
        if (t == GRID_BLOCKS - 1) {
            // Last block: finalize and reset for the next graph replay.
            out[0] = (float)(g_loss_sum / (double)N_QUERIES);
            out[1] = (float)g_correct / (float)N_QUERIES;
            g_loss_sum = 0.0;
            g_correct  = 0;
            g_ticket   = 0;
        }
    }
}

extern "C" void kernel_launch(void* const* d_in, const int* in_sizes, int n_in,
                              void* d_out, int out_size) {
    const float* qry    = (const float*)d_in[0];
    const float* prompt = (const float*)d_in[1];
    const float* labels = (const float*)d_in[2];
    float* out = (float*)d_out;

    proto_fused_kernel<<<GRID_BLOCKS, 256>>>(qry, prompt, labels, out);
}

// round 12
// speedup vs baseline: 1.1222x; 1.1222x over previous
#include <cuda_runtime.h>
#include <cuda_bf16.h>
#include <math.h>

#define N_QUERIES 8192
#define N_WAY 5
#define DIM 256
#define WARPS_PER_BLOCK 8
#define GRID_BLOCKS (N_QUERIES / WARPS_PER_BLOCK)   // 1024

// Accumulators. Zero at module load; the last finishing block resets them
// after producing the output, so every graph replay starts from zero.
__device__ double       g_loss_sum = 0.0;
__device__ int          g_correct  = 0;
__device__ unsigned int g_ticket   = 0;

__global__ __launch_bounds__(256) void proto_fused_kernel(
    const float* __restrict__ qry,      // [N, DIM]
    const float* __restrict__ prompt,   // [N*N_WAY, DIM]
    const float* __restrict__ labels,   // [N, N_WAY] one-hot
    float* __restrict__ out)            // [2]: loss, acc
{
    __shared__ float s_loss[WARPS_PER_BLOCK];
    __shared__ int   s_corr[WARPS_PER_BLOCK];

    const int warp_in_blk = threadIdx.x >> 5;
    const int lane        = threadIdx.x & 31;
    const int query       = blockIdx.x * WARPS_PER_BLOCK + warp_in_blk;

    // ---- per-query distance computation (one warp per query) ----
    const float4* q4 = reinterpret_cast<const float4*>(qry + (size_t)query * DIM);
    float4 qa = q4[lane];
    float4 qb = q4[lane + 32];

    float dist[N_WAY];
#pragma unroll
    for (int w = 0; w < N_WAY; ++w) {
        const float4* p4 = reinterpret_cast<const float4*>(
            prompt + ((size_t)query * N_WAY + w) * DIM);
        float4 pa = p4[lane];
        float4 pb = p4[lane + 32];
        float dx, s;
        dx = qa.x - pa.x; s  = dx * dx;
        dx = qa.y - pa.y; s += dx * dx;
        dx = qa.z - pa.z; s += dx * dx;
        dx = qa.w - pa.w; s += dx * dx;
        dx = qb.x - pb.x; s += dx * dx;
        dx = qb.y - pb.y; s += dx * dx;
        dx = qb.z - pb.z; s += dx * dx;
        dx = qb.w - pb.w; s += dx * dx;
        dist[w] = s;
    }

#pragma unroll
    for (int off = 16; off > 0; off >>= 1) {
#pragma unroll
        for (int w = 0; w < N_WAY; ++w)
            dist[w] += __shfl_xor_sync(0xFFFFFFFFu, dist[w], off);
    }

    if (lane == 0) {
        float mind = dist[0];
        int   amin = 0;
#pragma unroll
        for (int w = 1; w < N_WAY; ++w)
            if (dist[w] < mind) { mind = dist[w]; amin = w; }

        float sumexp = 0.0f;
#pragma unroll
        for (int w = 0; w < N_WAY; ++w)
            sumexp += __expf(mind - dist[w]);
        float lse = logf(sumexp);

        const float* lbl = labels + (size_t)query * N_WAY;
        int label = 0;
#pragma unroll
        for (int w = N_WAY - 1; w >= 1; --w)
            if (lbl[w] > 0.5f) label = w;

        float logp = (mind - dist[label]) - lse;   // log_softmax at label
        s_loss[warp_in_blk] = -logp;
        s_corr[warp_in_blk] = (amin == label) ? 1 : 0;
    }
    __syncthreads();

    // ---- block reduce + single atomic per block ----
    if (threadIdx.x == 0) {
        float bl = 0.0f;
        int   bc = 0;
#pragma unroll
        for (int i = 0; i < WARPS_PER_BLOCK; ++i) { bl += s_loss[i]; bc += s_corr[i]; }
        atomicAdd(&g_loss_sum, (double)bl);
        atomicAdd(&g_correct, bc);

        __threadfence();
        unsigned int t = atomicAdd(&g_ticket, 1u);
        if (t == GRID_BLOCKS - 1) {
            // Last block: finalize and reset for the next graph replay.
            out[0] = (float)(g_loss_sum / (double)N_QUERIES);
            out[1] = (float)g_correct / (float)N_QUERIES;
            g_loss_sum = 0.0;
            g_correct  = 0;
            g_ticket   = 0;
        }
    }
}

extern "C" void kernel_launch(void* const* d_in, const int* in_sizes, int n_in,
                              void* d_out, int out_size) {
    const float* qry    = (const float*)d_in[0];
    const float* prompt = (const float*)d_in[1];
    const float* labels = (const float*)d_in[2];
    float* out = (float*)d_out;

    proto_fused_kernel<<<GRID_BLOCKS, 256>>>(qry, prompt, labels, out);
}